// round 11
// baseline (speedup 1.0000x reference)
#include <cuda_runtime.h>
#include <math.h>

#define B_      8
#define K_      256
#define DIM_    50257
#define KNN_    8
#define NCLASS_ 4
#define NCHUNK_ 4
#define CHUNK_  12565               // ceil(DIM/4); last chunk is 12562
#define NBLK_   (B_ * K_ / 2 * NCHUNK_)   // 4096
#define SCALE_  (-1.0f / (0.05f * (float)DIM_))

typedef unsigned long long u64;

__device__ float g_ll[B_ * DIM_];            // log(logits)
__device__ float g_part[NCHUNK_][B_ * K_];   // per-chunk partial scaled dists
__device__ int   g_cnt = 0;                  // completion counter (self-resetting)

// ---------------------------------------------------------------------------
// Packed f32x2 helpers (sm_103a)
// ---------------------------------------------------------------------------
__device__ __forceinline__ u64 pk(float lo, float hi) {
    u64 r; asm("mov.b64 %0, {%1, %2};" : "=l"(r) : "f"(lo), "f"(hi)); return r;
}
__device__ __forceinline__ u64 bcast(float c) {
    unsigned u = __float_as_uint(c); return ((u64)u << 32) | (u64)u;
}
__device__ __forceinline__ void unpk(u64 v, float& lo, float& hi) {
    asm("mov.b64 {%0, %1}, %2;" : "=f"(lo), "=f"(hi) : "l"(v));
}
__device__ __forceinline__ u64 fma2(u64 a, u64 b, u64 c) {
    u64 d; asm("fma.rn.f32x2 %0, %1, %2, %3;" : "=l"(d) : "l"(a), "l"(b), "l"(c)); return d;
}
__device__ __forceinline__ u64 add2(u64 a, u64 b) {
    u64 d; asm("add.rn.f32x2 %0, %1, %2;" : "=l"(d) : "l"(a), "l"(b)); return d;
}

// ---------------------------------------------------------------------------
// Fast log via I2F identity, degree-5 economized polynomial (abs err ~1e-4;
// same formula on qa and logits sides so the common component cancels).
// ---------------------------------------------------------------------------
#define LOG_K1  8.2629584e-8f
#define LOG_C5  8.2304527e-4f
#define LOG_C4 -3.4293560e-3f
#define LOG_C3  1.2345679e-2f
#define LOG_C2 -5.5426958e-2f
#define LOG_C1 -1.3240266e-2f
#define LOG_C0 -87.970807f

__device__ __forceinline__ float fastlog_s(float x) {
    unsigned ix = __float_as_uint(x);
    float m  = __uint_as_float((ix & 0x7fffffu) | 0x3f800000u);
    float fi = (float)(int)ix;
    float w  = fmaf(m, 2.0f, -3.0f);
    float q  = LOG_C5;
    q = fmaf(q, w, LOG_C4);
    q = fmaf(q, w, LOG_C3);
    q = fmaf(q, w, LOG_C2);
    q = fmaf(q, w, LOG_C1);
    q = fmaf(q, w, LOG_C0);
    return fmaf(fi, LOG_K1, q);
}

__device__ __forceinline__ u64 plog2(float x0, float x1) {
    unsigned i0 = __float_as_uint(x0), i1 = __float_as_uint(x1);
    float m0  = __uint_as_float((i0 & 0x7fffffu) | 0x3f800000u);
    float m1  = __uint_as_float((i1 & 0x7fffffu) | 0x3f800000u);
    float fi0 = (float)(int)i0;
    float fi1 = (float)(int)i1;
    u64 w = fma2(pk(m0, m1), bcast(2.0f), bcast(-3.0f));
    u64 q = bcast(LOG_C5);
    q = fma2(q, w, bcast(LOG_C4));
    q = fma2(q, w, bcast(LOG_C3));
    q = fma2(q, w, bcast(LOG_C2));
    q = fma2(q, w, bcast(LOG_C1));
    q = fma2(q, w, bcast(LOG_C0));
    return fma2(pk(fi0, fi1), bcast(LOG_K1), q);
}

// ---------------------------------------------------------------------------
// Kernel 1: log of logits — float4 (402056 elems, divisible by 4)
// ---------------------------------------------------------------------------
__global__ void k_log(const float* __restrict__ logits) {
    int i = blockIdx.x * blockDim.x + threadIdx.x;
    if (i < (B_ * DIM_) / 4) {
        float4 x = ((const float4*)logits)[i];
        float4 y;
        y.x = fastlog_s(x.x); y.y = fastlog_s(x.y);
        y.z = fastlog_s(x.z); y.w = fastlog_s(x.w);
        ((float4*)g_ll)[i] = y;
    }
}

// ---------------------------------------------------------------------------
// Kernel 2: R8 k_dist verbatim + fused top-k tail in the LAST block
// (threadfence-reduction pattern). grid = (1024, 4); 256 threads.
// ---------------------------------------------------------------------------
__global__ void __launch_bounds__(256) k_dist(const float* __restrict__ qa,
                                              const int* __restrict__ qlabel,
                                              float* __restrict__ out) {
    const int pair  = blockIdx.x;
    const int chunk = blockIdx.y;
    const int b     = pair >> 7;
    const int k0    = (pair & 127) * 2;

    const int dbeg = chunk * CHUNK_;
    const int dlen = (dbeg + CHUNK_ <= DIM_) ? CHUNK_ : (DIM_ - dbeg);

    const float* __restrict__ ll = g_ll + (size_t)b * DIM_ + dbeg;
    const float* __restrict__ q0 = qa + ((size_t)(b * K_ + k0)) * DIM_ + dbeg;
    const float* __restrict__ q1 = q0 + DIM_;

    const u64 NEG1 = bcast(-1.0f);
    u64 acc[4] = {0ull, 0ull, 0ull, 0ull};

    int d = threadIdx.x;
    for (; d + 768 < dlen; d += 1024) {
        float l[4], x0[4], x1[4];
        #pragma unroll
        for (int j = 0; j < 4; j++) {
            int e = d + j * 256;
            l[j]  = __ldg(ll + e);
            x0[j] = __ldcs(q0 + e);
            x1[j] = __ldcs(q1 + e);
        }
        #pragma unroll
        for (int j = 0; j < 4; j++) {
            u64 diff = fma2(pk(l[j], l[j]), NEG1, plog2(x0[j], x1[j]));
            acc[j] = fma2(pk(x0[j], x1[j]), diff, acc[j]);
        }
    }
    for (; d < dlen; d += 256) {
        float l  = __ldg(ll + d);
        float x0 = __ldcs(q0 + d);
        float x1 = __ldcs(q1 + d);
        u64 diff = fma2(pk(l, l), NEG1, plog2(x0, x1));
        acc[0] = fma2(pk(x0, x1), diff, acc[0]);
    }

    float a0, a1;
    unpk(add2(add2(acc[0], acc[1]), add2(acc[2], acc[3])), a0, a1);

    #pragma unroll
    for (int s = 16; s > 0; s >>= 1) {
        a0 += __shfl_xor_sync(0xFFFFFFFFu, a0, s);
        a1 += __shfl_xor_sync(0xFFFFFFFFu, a1, s);
    }
    __shared__ float s0[8], s1[8];
    const int wid = threadIdx.x >> 5;
    const int lid = threadIdx.x & 31;
    if (lid == 0) { s0[wid] = a0; s1[wid] = a1; }
    __syncthreads();
    if (threadIdx.x == 0) {
        float t0 = 0.0f, t1 = 0.0f;
        #pragma unroll
        for (int w = 0; w < 8; w++) { t0 += s0[w]; t1 += s1[w]; }
        g_part[chunk][b * K_ + k0]     = t0 * SCALE_;
        g_part[chunk][b * K_ + k0 + 1] = t1 * SCALE_;
    }

    // ---- fused top-k tail: last block to finish does the epilogue ----
    __shared__ int isLast;
    if (threadIdx.x == 0) {
        __threadfence();                       // publish g_part writes
        int n = atomicAdd(&g_cnt, 1);
        isLast = (n == NBLK_ - 1);
        if (isLast) g_cnt = 0;                 // reset for next graph replay
    }
    __syncthreads();
    if (!isLast) return;

    // All 4096 g_part entries are visible (fences ordered writes before the
    // atomic increments). Warp w handles batch b = w.
    const int w    = threadIdx.x >> 5;
    const int lane = threadIdx.x & 31;

    float v[8];
    #pragma unroll
    for (int j = 0; j < 8; j++) {
        int idx = w * K_ + j * 32 + lane;
        float s = g_part[0][idx];
        #pragma unroll
        for (int c = 1; c < NCHUNK_; c++) s += g_part[c][idx];
        v[j] = s;
    }

    float topv[KNN_];
    int   topi[KNN_];
    #pragma unroll
    for (int r = 0; r < KNN_; r++) {
        float bv = -INFINITY; int bi = K_;
        #pragma unroll
        for (int j = 0; j < 8; j++) {
            int idx = j * 32 + lane;
            if (v[j] > bv) { bv = v[j]; bi = idx; }
        }
        #pragma unroll
        for (int s = 16; s > 0; s >>= 1) {
            float ov = __shfl_xor_sync(0xFFFFFFFFu, bv, s);
            int   oi = __shfl_xor_sync(0xFFFFFFFFu, bi, s);
            if (ov > bv || (ov == bv && oi < bi)) { bv = ov; bi = oi; }
        }
        topv[r] = bv; topi[r] = bi;
        if ((bi & 31) == lane) v[bi >> 5] = -INFINITY;
    }

    if (lane == 0) {
        float mx = topv[0];
        float wt[KNN_], sum = 0.0f;
        #pragma unroll
        for (int r = 0; r < KNN_; r++) { wt[r] = expf(topv[r] - mx); sum += wt[r]; }
        float inv = 1.0f / sum;
        float o[NCLASS_] = {0.0f, 0.0f, 0.0f, 0.0f};
        #pragma unroll
        for (int r = 0; r < KNN_; r++)
            o[qlabel[w * K_ + topi[r]]] += wt[r] * inv;
        #pragma unroll
        for (int c = 0; c < NCLASS_; c++) out[w * NCLASS_ + c] = o[c];
    }
}

// ---------------------------------------------------------------------------
// Launch
// ---------------------------------------------------------------------------
extern "C" void kernel_launch(void* const* d_in, const int* in_sizes, int n_in,
                              void* d_out, int out_size) {
    const float* logits = nullptr;
    const float* qa     = nullptr;
    const int*   qlabel = nullptr;
    for (int i = 0; i < n_in; i++) {
        if (in_sizes[i] == B_ * DIM_)           logits = (const float*)d_in[i];
        else if (in_sizes[i] == B_ * K_ * DIM_) qa     = (const float*)d_in[i];
        else if (in_sizes[i] == B_ * K_)        qlabel = (const int*)d_in[i];
    }
    float* out = (float*)d_out;

    k_log <<<((B_ * DIM_) / 4 + 255) / 256, 256>>>(logits);
    dim3 dg(B_ * K_ / 2, NCHUNK_);
    k_dist<<<dg, 256>>>(qa, qlabel, out);
}

// round 12
// speedup vs baseline: 1.2010x; 1.2010x over previous
#include <cuda_runtime.h>
#include <math.h>

#define B_      8
#define K_      256
#define DIM_    50257
#define KNN_    8
#define NCLASS_ 4
#define NCHUNK_ 4
#define CHUNK_  12565               // ceil(DIM/4); last chunk is 12562
#define SCALE_  (-1.0f / (0.05f * (float)DIM_))

typedef unsigned long long u64;

__device__ float g_ll[B_ * DIM_];            // log(logits)
__device__ float g_part[NCHUNK_][B_ * K_];   // per-chunk partial scaled dists

// ---------------------------------------------------------------------------
// Packed f32x2 helpers (sm_103a)
// ---------------------------------------------------------------------------
__device__ __forceinline__ u64 pk(float lo, float hi) {
    u64 r; asm("mov.b64 %0, {%1, %2};" : "=l"(r) : "f"(lo), "f"(hi)); return r;
}
__device__ __forceinline__ u64 bcast(float c) {
    unsigned u = __float_as_uint(c); return ((u64)u << 32) | (u64)u;
}
__device__ __forceinline__ void unpk(u64 v, float& lo, float& hi) {
    asm("mov.b64 {%0, %1}, %2;" : "=f"(lo), "=f"(hi) : "l"(v));
}
__device__ __forceinline__ u64 fma2(u64 a, u64 b, u64 c) {
    u64 d; asm("fma.rn.f32x2 %0, %1, %2, %3;" : "=l"(d) : "l"(a), "l"(b), "l"(c)); return d;
}
__device__ __forceinline__ u64 add2(u64 a, u64 b) {
    u64 d; asm("add.rn.f32x2 %0, %1, %2;" : "=l"(d) : "l"(a), "l"(b)); return d;
}

// ---------------------------------------------------------------------------
// Fast log via I2F identity, degree-5 economized polynomial (abs err ~1e-4;
// same formula on qa and logits sides so the common component cancels).
// ---------------------------------------------------------------------------
#define LOG_K1  8.2629584e-8f
#define LOG_C5  8.2304527e-4f
#define LOG_C4 -3.4293560e-3f
#define LOG_C3  1.2345679e-2f
#define LOG_C2 -5.5426958e-2f
#define LOG_C1 -1.3240266e-2f
#define LOG_C0 -87.970807f

__device__ __forceinline__ float fastlog_s(float x) {
    unsigned ix = __float_as_uint(x);
    float m  = __uint_as_float((ix & 0x7fffffu) | 0x3f800000u);
    float fi = (float)(int)ix;
    float w  = fmaf(m, 2.0f, -3.0f);
    float q  = LOG_C5;
    q = fmaf(q, w, LOG_C4);
    q = fmaf(q, w, LOG_C3);
    q = fmaf(q, w, LOG_C2);
    q = fmaf(q, w, LOG_C1);
    q = fmaf(q, w, LOG_C0);
    return fmaf(fi, LOG_K1, q);
}

__device__ __forceinline__ u64 plog2(float x0, float x1) {
    unsigned i0 = __float_as_uint(x0), i1 = __float_as_uint(x1);
    float m0  = __uint_as_float((i0 & 0x7fffffu) | 0x3f800000u);
    float m1  = __uint_as_float((i1 & 0x7fffffu) | 0x3f800000u);
    float fi0 = (float)(int)i0;
    float fi1 = (float)(int)i1;
    u64 w = fma2(pk(m0, m1), bcast(2.0f), bcast(-3.0f));
    u64 q = bcast(LOG_C5);
    q = fma2(q, w, bcast(LOG_C4));
    q = fma2(q, w, bcast(LOG_C3));
    q = fma2(q, w, bcast(LOG_C2));
    q = fma2(q, w, bcast(LOG_C1));
    q = fma2(q, w, bcast(LOG_C0));
    return fma2(pk(fi0, fi1), bcast(LOG_K1), q);
}

// ---------------------------------------------------------------------------
// Kernel 1: log of logits — float4 (402056 elems, divisible by 4)
// ---------------------------------------------------------------------------
__global__ void k_log(const float* __restrict__ logits) {
    int i = blockIdx.x * blockDim.x + threadIdx.x;
    if (i < (B_ * DIM_) / 4) {
        float4 x = ((const float4*)logits)[i];
        float4 y;
        y.x = fastlog_s(x.x); y.y = fastlog_s(x.y);
        y.z = fastlog_s(x.z); y.w = fastlog_s(x.w);
        ((float4*)g_ll)[i] = y;
    }
}

// ---------------------------------------------------------------------------
// Kernel 2: rows (b,k0) and (b,k0+1), one D-chunk per block — R8 verbatim,
// EXCEPT __launch_bounds__(256, 6): force >=6 blocks/SM (~42 regs) to lift
// occupancy 48% -> ~75% and with it the in-flight DRAM load count.
// grid = (B*K/2, NCHUNK) = (1024, 4); 256 threads.
// ---------------------------------------------------------------------------
__global__ void __launch_bounds__(256, 6) k_dist(const float* __restrict__ qa) {
    const int pair  = blockIdx.x;
    const int chunk = blockIdx.y;
    const int b     = pair >> 7;
    const int k0    = (pair & 127) * 2;

    const int dbeg = chunk * CHUNK_;
    const int dlen = (dbeg + CHUNK_ <= DIM_) ? CHUNK_ : (DIM_ - dbeg);

    const float* __restrict__ ll = g_ll + (size_t)b * DIM_ + dbeg;
    const float* __restrict__ q0 = qa + ((size_t)(b * K_ + k0)) * DIM_ + dbeg;
    const float* __restrict__ q1 = q0 + DIM_;

    const u64 NEG1 = bcast(-1.0f);
    u64 acc[4] = {0ull, 0ull, 0ull, 0ull};

    int d = threadIdx.x;
    for (; d + 768 < dlen; d += 1024) {
        float l[4], x0[4], x1[4];
        #pragma unroll
        for (int j = 0; j < 4; j++) {
            int e = d + j * 256;
            l[j]  = __ldg(ll + e);
            x0[j] = __ldcs(q0 + e);
            x1[j] = __ldcs(q1 + e);
        }
        #pragma unroll
        for (int j = 0; j < 4; j++) {
            u64 diff = fma2(pk(l[j], l[j]), NEG1, plog2(x0[j], x1[j]));
            acc[j] = fma2(pk(x0[j], x1[j]), diff, acc[j]);
        }
    }
    for (; d < dlen; d += 256) {
        float l  = __ldg(ll + d);
        float x0 = __ldcs(q0 + d);
        float x1 = __ldcs(q1 + d);
        u64 diff = fma2(pk(l, l), NEG1, plog2(x0, x1));
        acc[0] = fma2(pk(x0, x1), diff, acc[0]);
    }

    float a0, a1;
    unpk(add2(add2(acc[0], acc[1]), add2(acc[2], acc[3])), a0, a1);

    #pragma unroll
    for (int s = 16; s > 0; s >>= 1) {
        a0 += __shfl_xor_sync(0xFFFFFFFFu, a0, s);
        a1 += __shfl_xor_sync(0xFFFFFFFFu, a1, s);
    }
    __shared__ float s0[8], s1[8];
    const int wid = threadIdx.x >> 5;
    const int lid = threadIdx.x & 31;
    if (lid == 0) { s0[wid] = a0; s1[wid] = a1; }
    __syncthreads();
    if (threadIdx.x == 0) {
        float t0 = 0.0f, t1 = 0.0f;
        #pragma unroll
        for (int w = 0; w < 8; w++) { t0 += s0[w]; t1 += s1[w]; }
        g_part[chunk][b * K_ + k0]     = t0 * SCALE_;
        g_part[chunk][b * K_ + k0 + 1] = t1 * SCALE_;
    }
}

// ---------------------------------------------------------------------------
// Kernel 3: one block, warp w = batch b. Sums the 4 chunk partials, then
// warp-shuffle top-8 (jax tie-break: lowest index), softmax, class scatter.
// ---------------------------------------------------------------------------
__global__ void __launch_bounds__(256) k_topk(const int* __restrict__ qlabel,
                                              float* __restrict__ out) {
    const int w    = threadIdx.x >> 5;
    const int lane = threadIdx.x & 31;

    float v[8];
    #pragma unroll
    for (int j = 0; j < 8; j++) {
        int idx = w * K_ + j * 32 + lane;
        float s = g_part[0][idx];
        #pragma unroll
        for (int c = 1; c < NCHUNK_; c++) s += g_part[c][idx];
        v[j] = s;
    }

    float topv[KNN_];
    int   topi[KNN_];
    #pragma unroll
    for (int r = 0; r < KNN_; r++) {
        float bv = -INFINITY; int bi = K_;
        #pragma unroll
        for (int j = 0; j < 8; j++) {
            int idx = j * 32 + lane;
            if (v[j] > bv) { bv = v[j]; bi = idx; }
        }
        #pragma unroll
        for (int s = 16; s > 0; s >>= 1) {
            float ov = __shfl_xor_sync(0xFFFFFFFFu, bv, s);
            int   oi = __shfl_xor_sync(0xFFFFFFFFu, bi, s);
            if (ov > bv || (ov == bv && oi < bi)) { bv = ov; bi = oi; }
        }
        topv[r] = bv; topi[r] = bi;
        if ((bi & 31) == lane) v[bi >> 5] = -INFINITY;
    }

    if (lane == 0) {
        float mx = topv[0];
        float wt[KNN_], sum = 0.0f;
        #pragma unroll
        for (int r = 0; r < KNN_; r++) { wt[r] = expf(topv[r] - mx); sum += wt[r]; }
        float inv = 1.0f / sum;
        float o[NCLASS_] = {0.0f, 0.0f, 0.0f, 0.0f};
        #pragma unroll
        for (int r = 0; r < KNN_; r++)
            o[qlabel[w * K_ + topi[r]]] += wt[r] * inv;
        #pragma unroll
        for (int c = 0; c < NCLASS_; c++) out[w * NCLASS_ + c] = o[c];
    }
}

// ---------------------------------------------------------------------------
// Launch
// ---------------------------------------------------------------------------
extern "C" void kernel_launch(void* const* d_in, const int* in_sizes, int n_in,
                              void* d_out, int out_size) {
    const float* logits = nullptr;
    const float* qa     = nullptr;
    const int*   qlabel = nullptr;
    for (int i = 0; i < n_in; i++) {
        if (in_sizes[i] == B_ * DIM_)           logits = (const float*)d_in[i];
        else if (in_sizes[i] == B_ * K_ * DIM_) qa     = (const float*)d_in[i];
        else if (in_sizes[i] == B_ * K_)        qlabel = (const int*)d_in[i];
    }
    float* out = (float*)d_out;

    k_log <<<((B_ * DIM_) / 4 + 255) / 256, 256>>>(logits);
    dim3 dg(B_ * K_ / 2, NCHUNK_);
    k_dist<<<dg, 256>>>(qa);
    k_topk<<<1, 256>>>(qlabel, out);
}